// round 15
// baseline (speedup 1.0000x reference)
#include <cuda_runtime.h>
#include <cstdint>

#define NN     256
#define BB     8
#define SS     14
#define BS     (BB*SS)
#define NDAT   12      // S - len(PILOTS)
#define VMAX   4       // members per work unit

__device__ float2 g_h[BS * NN];        // DFT(x)*conj(zc), bs-major
__device__ int    g_idx[BS];           // cov index per bs
__device__ int    g_members[BS * BS];  // member lists, slot-major (slot*112+pos)
__device__ int4   g_units[BS * 4];     // (covIdx, memberBase, V, part)
__device__ int    g_nu_dev;

// ---------------------------------------------------------------------------
// Kernel 1: per-(b,s) 256-pt DFT (radix-16 x radix-16) * conj(zc) -> g_h.
// ---------------------------------------------------------------------------
__global__ void __launch_bounds__(NN)
prep_kernel(const float* __restrict__ xr,
            const float* __restrict__ xi,
            const float* __restrict__ zr,
            const float* __restrict__ zi,
            const int*   __restrict__ shift,
            const int*   __restrict__ gidx)
{
    __shared__ float2 xs[16 * 17];
    __shared__ float2 aa[17 * 16];
    __shared__ float2 w16[16];

    const int bs  = blockIdx.x;
    const int b   = bs / SS;
    const int s   = bs % SS;
    const int tid = threadIdx.x;

    if (tid == 0) {
        const int g = gidx[s];
        g_idx[bs]   = (g == 0) ? 0 : shift[b * NDAT + g - 1];
    }

    xs[(tid & 15) * 17 + (tid >> 4)] = make_float2(xr[bs * NN + tid],
                                                   xi[bs * NN + tid]);
    if (tid < 16) {
        float sn, cs;
        sincospif(-(float)tid * 0.125f, &sn, &cs);       // e^{-2pi i t/16}
        w16[tid] = make_float2(cs, sn);
    }
    __syncthreads();

    {   // stage A
        const int k0 = tid >> 4, n0 = tid & 15;
        float ar = 0.0f, ai = 0.0f;
#pragma unroll
        for (int n1 = 0; n1 < 16; n1++) {
            const float2 v  = xs[n0 * 17 + n1];
            const float2 ww = w16[(k0 * n1) & 15];
            ar = fmaf(v.x, ww.x, fmaf(-v.y, ww.y, ar));
            ai = fmaf(v.x, ww.y, fmaf( v.y, ww.x, ai));
        }
        float sn, cs;
        sincospif(-(float)(k0 * n0) * (1.0f / 128.0f), &sn, &cs);
        aa[n0 * 17 + k0] = make_float2(ar * cs - ai * sn, ar * sn + ai * cs);
    }
    __syncthreads();

    {   // stage B + conj(zc)
        const int k0 = tid & 15, k1 = tid >> 4;
        float Xr = 0.0f, Xi = 0.0f;
#pragma unroll
        for (int n0 = 0; n0 < 16; n0++) {
            const float2 v  = aa[n0 * 17 + k0];
            const float2 ww = w16[(k1 * n0) & 15];
            Xr = fmaf(v.x, ww.x, fmaf(-v.y, ww.y, Xr));
            Xi = fmaf(v.x, ww.y, fmaf( v.y, ww.x, Xi));
        }
        const float a  = zr[tid];
        const float bq = -zi[tid];
        g_h[bs * NN + tid] = make_float2(Xr * a - Xi * bq, Xr * bq + Xi * a);
    }
}

// ---------------------------------------------------------------------------
// Kernel 2: group the 112 bs by unique cov index; emit work units
// (covIdx, memberBase, V<=4, part of 64 rows). Single block.
// Unit order depends on atomics but each member's output is identical
// regardless of ordering -> results deterministic.
// ---------------------------------------------------------------------------
__global__ void __launch_bounds__(128)
group_kernel()
{
    __shared__ int idxv[BS], lead[BS], slotOf[BS], scov[BS], cnt[BS];
    __shared__ int nslots, nu;

    const int t = threadIdx.x;
    if (t == 0) { nslots = 0; nu = 0; }
    if (t < BS) { idxv[t] = g_idx[t]; cnt[t] = 0; }
    __syncthreads();

    if (t < BS) {
        int ld = t;
        for (int u = 0; u < BS; u++)
            if (idxv[u] == idxv[t]) { ld = u; break; }
        lead[t] = ld;
    }
    __syncthreads();

    if (t < BS && lead[t] == t) {
        const int s = atomicAdd(&nslots, 1);
        slotOf[t] = s;
        scov[s]   = idxv[t];
    }
    __syncthreads();

    if (t < BS) {
        const int s = slotOf[lead[t]];
        const int p = atomicAdd(&cnt[s], 1);
        g_members[s * BS + p] = t;
    }
    __syncthreads();

    if (t < BS && t < nslots) {           // t = slot id
        const int c  = cnt[t];
        const int np = (c + VMAX - 1) / VMAX;
        int k = atomicAdd(&nu, np * 4);
        for (int mb = 0; mb < c; mb += VMAX)
            for (int part = 0; part < 4; part++)
                g_units[k++] = make_int4(scov[t], t * BS + mb,
                                         min(VMAX, c - mb), part);
    }
    __syncthreads();
    if (t == 0) g_nu_dev = nu;
}

// ---------------------------------------------------------------------------
// Kernel 3: batched matvec. Grid = 448 blocks x 256 threads; block = one unit
// (cov idx, <=4 h vectors, 64 rows). R7-style 2-deep LDG ring streams the cov
// rows once; each row is dotted with all V member h vectors (h transposed in
// smem, conflict-free LDS.64 reads).
// ---------------------------------------------------------------------------
__global__ void __launch_bounds__(256)
matvec_grouped(const float* __restrict__ cr,
               const float* __restrict__ ci,
               float*       __restrict__ out)
{
    __shared__ float2 hT[VMAX * NN];   // hT[v][j*32+l] = h_v[8l+j]
    __shared__ int    oBase[VMAX];

    if (blockIdx.x >= g_nu_dev) return;
    const int4 U   = g_units[blockIdx.x];
    const int  V   = U.z;
    const int  tid = threadIdx.x;
    const int  w   = tid >> 5;
    const int  lane = tid & 31;
    const int  rowBase = U.w * 64;

    const size_t  base = (size_t)U.x * NN * NN;
    const float4* cr4  = (const float4*)(cr + base);
    const float4* ci4  = (const float4*)(ci + base);

    // ---- prologue: ring fill tiles 0..1 ----
    float4 A[2][2], C[2][2];
#pragma unroll
    for (int p = 0; p < 2; p++) {
        const size_t ro = (size_t)(rowBase + p * 8 + w) * 64 + lane * 2;
        A[p][0] = cr4[ro];  A[p][1] = cr4[ro + 1];
        C[p][0] = ci4[ro];  C[p][1] = ci4[ro + 1];
    }

    // ---- load member h vectors into transposed smem (overlaps ring fill) ----
    {
        const int j = tid >> 5, l = tid & 31;    // m = 8l + j
        for (int v = 0; v < V; v++) {
            const int bs = g_members[U.y + v];
            hT[v * NN + j * 32 + l] = g_h[bs * NN + 8 * l + j];
            if (tid == 0) oBase[v] = bs * NN;
        }
    }
    __syncthreads();

    // ---- 8-tile streaming loop; each tile row dotted with V vectors ----
#pragma unroll
    for (int t = 0; t < 8; t++) {
        const int cur = t & 1;
        const float4 a0 = A[cur][0], a1 = A[cur][1];
        const float4 c0 = C[cur][0], c1 = C[cur][1];

        if (t < 6) {   // refill this stage with tile t+2
            const size_t ro = (size_t)(rowBase + (t + 2) * 8 + w) * 64 + lane * 2;
            A[cur][0] = cr4[ro];  A[cur][1] = cr4[ro + 1];
            C[cur][0] = ci4[ro];  C[cur][1] = ci4[ro + 1];
        }

        const int row = rowBase + t * 8 + w;

        for (int v = 0; v < V; v++) {
            const float2* hv = hT + v * NN;
            const float2 h0 = hv[0 * 32 + lane];
            const float2 h1 = hv[1 * 32 + lane];
            const float2 h2 = hv[2 * 32 + lane];
            const float2 h3 = hv[3 * 32 + lane];
            const float2 h4 = hv[4 * 32 + lane];
            const float2 h5 = hv[5 * 32 + lane];
            const float2 h6 = hv[6 * 32 + lane];
            const float2 h7 = hv[7 * 32 + lane];

            float re = 0.0f;
            re = fmaf(a0.x, h0.x, fmaf(-c0.x, h0.y, re));
            re = fmaf(a0.y, h1.x, fmaf(-c0.y, h1.y, re));
            re = fmaf(a0.z, h2.x, fmaf(-c0.z, h2.y, re));
            re = fmaf(a0.w, h3.x, fmaf(-c0.w, h3.y, re));
            re = fmaf(a1.x, h4.x, fmaf(-c1.x, h4.y, re));
            re = fmaf(a1.y, h5.x, fmaf(-c1.y, h5.y, re));
            re = fmaf(a1.z, h6.x, fmaf(-c1.z, h6.y, re));
            re = fmaf(a1.w, h7.x, fmaf(-c1.w, h7.y, re));

#pragma unroll
            for (int o = 16; o > 0; o >>= 1)
                re += __shfl_xor_sync(0xffffffffu, re, o);

            if (lane == 0) out[oBase[v] + row] = re;
        }
    }
}

extern "C" void kernel_launch(void* const* d_in, const int* in_sizes, int n_in,
                              void* d_out, int out_size)
{
    const float* xr    = (const float*)d_in[0];
    const float* xi    = (const float*)d_in[1];
    const float* cr    = (const float*)d_in[2];
    const float* ci    = (const float*)d_in[3];
    const float* zr    = (const float*)d_in[4];
    const float* zi    = (const float*)d_in[5];
    const int*   shift = (const int*)d_in[6];
    const int*   gidx  = (const int*)d_in[7];

    prep_kernel<<<BS, NN>>>(xr, xi, zr, zi, shift, gidx);
    group_kernel<<<1, 128>>>();
    matvec_grouped<<<BS * 4, 256>>>(cr, ci, (float*)d_out);
}